// round 16
// baseline (speedup 1.0000x reference)
#include <cuda_runtime.h>
#include <cstdint>

#define B_    4
#define T_    1024
#define DIM_  512
#define POOL_ 64
#define K_    50
#define TK_   2      // tokens per k1 block (packed in f32x2)
#define S_    8      // output-row slices per (b,j) source in k3_scatter

// Scratch (device globals: allocation-free per harness rules)
__device__ __align__(16) float g_y[B_ * POOL_ * POOL_];   // y[b][t<64][p]
__device__ __align__(16) float g_z[B_ * POOL_ * DIM_];    // z[b][j][d]
__device__ unsigned       g_member[T_ * 2];               // top-50 mask per t (2x u32)
__device__ unsigned char  g_rank[T_ * POOL_];             // rank of pool j in token t
__device__ unsigned short g_list[POOL_ * T_];             // per-j token list
__device__ int            g_cnt[POOL_];                   // per-j list length

// packed fp32x2 ops (Blackwell FFMA2 — only reachable via PTX)
#define FMA2(d, a, b) \
    asm("fma.rn.f32x2 %0, %1, %2, %3;" : "=l"(d) : "l"(a), "l"(b), "l"(d))
#define ADD2(d, a, b) \
    asm("add.rn.f32x2 %0, %1, %2;" : "=l"(d) : "l"(a), "l"(b))
#define UNPACK2(lo, hi, v) \
    asm("mov.b64 {%0, %1}, %2;" : "=f"(lo), "=f"(hi) : "l"(v))
#define LDS_V2U64(a0, a1, addr) \
    asm("ld.shared.v2.b64 {%0, %1}, [%2];" : "=l"(a0), "=l"(a1) : "r"(addr))

// ---------------------------------------------------------------------------
// Kernel 1 (round-5 config): 2 tokens/block, grid=512, block=256.
// f32x2 lanes = POOL PAIRS; x staged lane-duplicated in smem.
// Tail now also emits the top-50 membership mask (ballot) and per-(t,j) rank.
// ---------------------------------------------------------------------------
__global__ __launch_bounds__(256) void k1_reduce_topk(
        const float* __restrict__ x,
        const float* __restrict__ w1,
        const float* __restrict__ b1,
        const float* __restrict__ g1,
        const float* __restrict__ bt1) {
    __shared__ __align__(16) float2 pool2[B_ * TK_ * DIM_];  // 32KB
    __shared__ float sv[TK_ * POOL_];
    __shared__ float wsum[4][B_], wsq[4][B_];
    float* poolf = reinterpret_cast<float*>(pool2);

    const int t0  = blockIdx.x * TK_;
    const int tid = threadIdx.x;
    const int pg  = tid & 15;
    const int dc  = tid >> 4;

    uint32_t sx;
    asm("{ .reg .u64 t; cvta.to.shared.u64 t, %1; cvt.u32.u64 %0, t; }"
        : "=r"(sx) : "l"(pool2));

    // ---- phase 1: load x rows, lane-duplicated ----
    #pragma unroll
    for (int i = tid; i < B_ * (DIM_ / 4); i += 256) {
        int b = i >> 7, j = i & 127;
        const float* xb = x + ((size_t)b * T_ + t0) * DIM_;
        float4 v0 = reinterpret_cast<const float4*>(xb)[j];
        float4 v1 = reinterpret_cast<const float4*>(xb + DIM_)[j];
        float2* d0 = pool2 + (b * 2 + 0) * DIM_ + j * 4;
        d0[0] = make_float2(v0.x, v0.x);
        d0[1] = make_float2(v0.y, v0.y);
        d0[2] = make_float2(v0.z, v0.z);
        d0[3] = make_float2(v0.w, v0.w);
        float2* d1 = pool2 + (b * 2 + 1) * DIM_ + j * 4;
        d1[0] = make_float2(v1.x, v1.x);
        d1[1] = make_float2(v1.y, v1.y);
        d1[2] = make_float2(v1.z, v1.z);
        d1[3] = make_float2(v1.w, v1.w);
    }
    __syncthreads();

    // ---- main loop: 32 dims x 8 (b,tok) rows x 2 pool-pairs ----
    unsigned long long acc[8][2] = {};
    const ulonglong2* w1q = reinterpret_cast<const ulonglong2*>(w1);

    #pragma unroll 4
    for (int d2 = 0; d2 < 16; d2++) {
        const int d = dc * 32 + d2 * 2;
        ulonglong2 wd0 = __ldg(w1q + (size_t)d * 16 + pg);
        ulonglong2 wd1 = __ldg(w1q + (size_t)(d + 1) * 16 + pg);
        #pragma unroll
        for (int bt = 0; bt < 8; bt++) {
            unsigned long long xv0, xv1;
            LDS_V2U64(xv0, xv1, sx + (uint32_t)((bt * DIM_ + d) * 8));
            FMA2(acc[bt][0], xv0, wd0.x);
            FMA2(acc[bt][1], xv0, wd0.y);
            FMA2(acc[bt][0], xv1, wd1.x);
            FMA2(acc[bt][1], xv1, wd1.y);
        }
    }

    // ---- reduce over dc: butterfly (dc pairs), then smem ----
    #pragma unroll
    for (int bt = 0; bt < 8; bt++) {
        #pragma unroll
        for (int pr = 0; pr < 2; pr++) {
            unsigned long long o = __shfl_xor_sync(0xffffffffu, acc[bt][pr], 16);
            ADD2(acc[bt][pr], acc[bt][pr], o);
        }
    }
    __syncthreads();   // all x reads done; reuse poolf for partials

    if ((tid & 16) == 0) {
        const int w = tid >> 5;
        #pragma unroll
        for (int bt = 0; bt < 8; bt++) {
            #pragma unroll
            for (int pr = 0; pr < 2; pr++) {
                float lo, hi;
                UNPACK2(lo, hi, acc[bt][pr]);
                poolf[w * 512 + bt * 64 + pg * 4 + pr * 2 + 0] = lo;
                poolf[w * 512 + bt * 64 + pg * 4 + pr * 2 + 1] = hi;
            }
        }
    }
    __syncthreads();

    // ---- tail on first 128 threads: tk = tid>>6, pp = tid&63 ----
    float vv[B_];
    if (tid < TK_ * POOL_) {
        const int tk = tid >> 6;
        const int pp = tid & 63;
        const float bias = b1[pp];
        #pragma unroll
        for (int b = 0; b < B_; b++) {
            float a = bias;
            #pragma unroll
            for (int w = 0; w < 8; w++)
                a += poolf[w * 512 + (b * TK_ + tk) * 64 + pp];
            vv[b] = fmaxf(a, 0.f);
        }
        float s[B_], q[B_];
        #pragma unroll
        for (int b = 0; b < B_; b++) { s[b] = vv[b]; q[b] = vv[b] * vv[b]; }
        #pragma unroll
        for (int off = 16; off > 0; off >>= 1) {
            #pragma unroll
            for (int b = 0; b < B_; b++) {
                s[b] += __shfl_xor_sync(0xffffffffu, s[b], off);
                q[b] += __shfl_xor_sync(0xffffffffu, q[b], off);
            }
        }
        const int w = tid >> 5;
        if ((tid & 31) == 0) {
            #pragma unroll
            for (int b = 0; b < B_; b++) { wsum[w][b] = s[b]; wsq[w][b] = q[b]; }
        }
    }
    __syncthreads();

    if (tid < TK_ * POOL_) {
        const int tk = tid >> 6;
        const int pp = tid & 63;
        const int t  = t0 + tk;
        const float gp = g1[pp], bp = bt1[pp];

        float ysum = 0.f;
        float yv[B_];
        #pragma unroll
        for (int b = 0; b < B_; b++) {
            float S = wsum[tk * 2][b] + wsum[tk * 2 + 1][b];
            float Q = wsq[tk * 2][b]  + wsq[tk * 2 + 1][b];
            float m   = S * (1.f / POOL_);
            float var = Q * (1.f / POOL_) - m * m;
            float r   = rsqrtf(var + 1e-5f);
            yv[b] = (vv[b] - m) * r * gp + bp;
            ysum += yv[b];
        }

        if (t < POOL_) {
            #pragma unroll
            for (int b = 0; b < B_; b++)
                g_y[(b * POOL_ + t) * POOL_ + pp] = yv[b];
        }

        sv[tk * POOL_ + pp] = ysum;
        __syncwarp();
        asm volatile("bar.sync 1, 128;" ::: "memory");

        const float mine = ysum;
        int rank = 0;
        #pragma unroll
        for (int j = 0; j < POOL_; j++) {
            float o = sv[tk * POOL_ + j];
            rank += (o > mine) || ((o == mine) && (j < pp));
        }
        // membership mask (ballot over this warp's 32 pool slots) + rank table
        unsigned m = __ballot_sync(0xffffffffu, rank < K_);
        if ((tid & 31) == 0)
            g_member[t * 2 + ((tid >> 5) & 1)] = m;
        g_rank[t * POOL_ + pp] = (unsigned char)rank;
    }
}

// ---------------------------------------------------------------------------
// Kernel 2: z[b,j,:] = LN(relu(y[b,j,:] @ w2 + b2))   (256 distinct rows)
// grid = B_*POOL_, block = 512
// ---------------------------------------------------------------------------
__global__ void k2_expand(const float* __restrict__ w2,
                          const float* __restrict__ b2,
                          const float* __restrict__ g2,
                          const float* __restrict__ bt2) {
    const int bj = blockIdx.x;
    const int d  = threadIdx.x;

    __shared__ float yr[POOL_];
    if (d < POOL_) yr[d] = g_y[bj * POOL_ + d];
    __syncthreads();

    float acc = b2[d];
    #pragma unroll
    for (int p = 0; p < POOL_; p++)
        acc += yr[p] * w2[p * DIM_ + d];

    float v = fmaxf(acc, 0.f);

    float s = v, q = v * v;
    #pragma unroll
    for (int off = 16; off > 0; off >>= 1) {
        s += __shfl_xor_sync(0xffffffffu, s, off);
        q += __shfl_xor_sync(0xffffffffu, q, off);
    }
    __shared__ float ps[16], pq[16];
    const int w = d >> 5;
    if ((d & 31) == 0) { ps[w] = s; pq[w] = q; }
    __syncthreads();
    float S = 0.f, Q = 0.f;
    #pragma unroll
    for (int i = 0; i < 16; i++) { S += ps[i]; Q += pq[i]; }

    float m   = S * (1.f / DIM_);
    float var = Q * (1.f / DIM_) - m * m;
    g_z[bj * DIM_ + d] = (v - m) * rsqrtf(var + 1e-5f) * g2[d] + bt2[d];
}

// ---------------------------------------------------------------------------
// k_inv: build per-j token lists via block prefix scan (no atomics,
// deterministic). grid = 64 (one block per pool index j), block = 256.
// ---------------------------------------------------------------------------
__global__ void k_inv() {
    const int j   = blockIdx.x;
    const int tid = threadIdx.x;
    const int lane = tid & 31, w = tid >> 5;
    const int word = j >> 5;
    const unsigned bit = 1u << (j & 31);

    int vals[4];
    int c = 0;
    const int t0 = tid * 4;
    #pragma unroll
    for (int i = 0; i < 4; i++) {
        vals[i] = (g_member[(t0 + i) * 2 + word] & bit) ? 1 : 0;
        c += vals[i];
    }

    // warp inclusive scan of c
    int incl = c;
    #pragma unroll
    for (int off = 1; off < 32; off <<= 1) {
        int n = __shfl_up_sync(0xffffffffu, incl, off);
        if (lane >= off) incl += n;
    }
    __shared__ int wsums[8];
    if (lane == 31) wsums[w] = incl;
    __syncthreads();

    int base = 0;
    #pragma unroll
    for (int k = 0; k < 8; k++)
        base += (k < w) ? wsums[k] : 0;

    int pos = base + incl - c;    // exclusive prefix
    unsigned short* lst = g_list + j * T_;
    #pragma unroll
    for (int i = 0; i < 4; i++) {
        if (vals[i]) lst[pos++] = (unsigned short)(t0 + i);
    }
    if (tid == 0) {
        int tot = 0;
        #pragma unroll
        for (int k = 0; k < 8; k++) tot += wsums[k];
        g_cnt[j] = tot;
    }
}

// ---------------------------------------------------------------------------
// k3_scatter: inverted gather. Block = one (b, j, slice): holds z[b,j,:]
// in registers (16 floats/lane) and streams it to every output row
// (b, t, k) with idx[t,k] == j in its slice. Inner loop = index math +
// 4 STG.128 from registers — zero read stream against the 419 MB writes.
// grid = B_*POOL_*S_ = 2048, block = 512 (16 warps, warp-per-row).
// ---------------------------------------------------------------------------
__global__ __launch_bounds__(512) void k3_scatter(float* __restrict__ out) {
    const int bi = blockIdx.x;
    const int s  = bi & (S_ - 1);
    const int bj = bi >> 3;              // b*64 + j
    const int b  = bj >> 6;
    const int j  = bj & 63;

    const int lane = threadIdx.x & 31;
    const int w    = threadIdx.x >> 5;   // 16 warps

    // z row into registers
    const float4* zr = reinterpret_cast<const float4*>(g_z) + (size_t)bj * 128;
    float4 z0 = __ldg(zr + lane);
    float4 z1 = __ldg(zr + 32 + lane);
    float4 z2 = __ldg(zr + 64 + lane);
    float4 z3 = __ldg(zr + 96 + lane);

    const int n = g_cnt[j];
    const unsigned short* lst = g_list + j * T_;
    const unsigned char*  rnk = g_rank + j;

    for (int m = w; ; m += 16) {
        int r = s + S_ * m;
        if (r >= n) break;
        int t = lst[r];
        int k = rnk[t * POOL_];
        float4* dst = reinterpret_cast<float4*>(out)
                      + (size_t)((b * T_ + t) * K_ + k) * 128;
        __stcs(dst + lane,      z0);
        __stcs(dst + 32 + lane, z1);
        __stcs(dst + 64 + lane, z2);
        __stcs(dst + 96 + lane, z3);
    }
}

// ---------------------------------------------------------------------------
extern "C" void kernel_launch(void* const* d_in, const int* in_sizes, int n_in,
                              void* d_out, int out_size) {
    const float* x   = (const float*)d_in[0];
    const float* w1  = (const float*)d_in[1];
    const float* b1  = (const float*)d_in[2];
    const float* g1  = (const float*)d_in[3];
    const float* bt1 = (const float*)d_in[4];
    const float* w2  = (const float*)d_in[5];
    const float* b2  = (const float*)d_in[6];
    const float* g2  = (const float*)d_in[7];
    const float* bt2 = (const float*)d_in[8];
    float* out = (float*)d_out;

    k1_reduce_topk<<<T_ / TK_, 256>>>(x, w1, b1, g1, bt1);
    k2_expand<<<B_ * POOL_, DIM_>>>(w2, b2, g2, bt2);
    k_inv<<<POOL_, 256>>>();
    k3_scatter<<<B_ * POOL_ * S_, 512>>>(out);
}